// round 16
// baseline (speedup 1.0000x reference)
#include <cuda_runtime.h>
#include <cuda_bf16.h>

#define WS 7
#define DROP_PROB 0.1f
#define Hc 250          // H - WS + 1
#define Wc 250
#define Hdim 256
#define Wdim 256
#define MASK_ELEMS (Hdim * Wdim)        // 65536
#define MASK_VEC4  (MASK_ELEMS / 4)     // 16384 (power of two)
#define TOTAL_VEC4 (16u * 64u * MASK_VEC4)   // 16777216

// [256,256] broadcast mask (device global scratch; no allocs allowed).
__device__ __align__(16) float g_mask[MASK_ELEMS];

// Kernel 1 (separable 7x7 max-dilation): one block per output row h. ~2us.
__global__ void build_mask_kernel(const float* __restrict__ u) {
    __shared__ int colOR[Wdim];
    int h = blockIdx.x;
    int w = threadIdx.x;

    int v = 0;
    if (w < Wc) {
        int a0 = h - (WS - 1); if (a0 < 0) a0 = 0;
        int a1 = h;            if (a1 > Hc - 1) a1 = Hc - 1;
        #pragma unroll 7
        for (int a = a0; a <= a1; ++a)
            v |= (__ldg(u + a * Wc + w) < DROP_PROB);
    }
    colOR[w] = v;
    __syncthreads();

    int b0 = w - (WS - 1); if (b0 < 0) b0 = 0;
    int b1 = w;            if (b1 > Wc - 1) b1 = Wc - 1;
    int d = 0;
    #pragma unroll 7
    for (int b = b0; b <= b1; ++b)
        d |= colOR[b];

    g_mask[h * Wdim + w] = d ? 0.0f : 1.0f;
}

// Kernel 2: R2's proven linear-sweep structure (6.5 TB/s measured) + read
// guard only. One float4 per thread, grid covers memory in a single linear
// sweep — the addressing pattern that matches memset's 7.3 TB/s behavior.
// Guard skips the x load for fully-dropped positions (~90%+ of pixels),
// cutting read traffic ~256MB -> ~10-25MB while keeping the sweep intact.
__global__ void __launch_bounds__(256, 8)
apply_mask_kernel(const float4* __restrict__ x, float4* __restrict__ out) {
    unsigned int i = blockIdx.x * 256u + threadIdx.x;
    const float4* m4 = reinterpret_cast<const float4*>(g_mask);
    float4 mv = __ldg(m4 + (i & (MASK_VEC4 - 1)));

    float4 o = make_float4(0.f, 0.f, 0.f, 0.f);
    if ((mv.x + mv.y + mv.z + mv.w) != 0.0f) {
        float4 xv = x[i];
        o.x = xv.x * mv.x;
        o.y = xv.y * mv.y;
        o.z = xv.z * mv.z;
        o.w = xv.w * mv.w;
    }
    out[i] = o;
}

extern "C" void kernel_launch(void* const* d_in, const int* in_sizes, int n_in,
                              void* d_out, int out_size) {
    const float* x = (const float*)d_in[0];   // [16,64,256,256] fp32
    const float* u = (const float*)d_in[1];   // [250,250] fp32
    float* out = (float*)d_out;

    // 1) 256x256 dilated mask (L2-resident, 256KB)
    build_mask_kernel<<<Hdim, Wdim>>>(u);

    // 2) guarded linear-sweep apply: one float4 per thread, 65536 blocks
    apply_mask_kernel<<<TOTAL_VEC4 / 256, 256>>>(
        reinterpret_cast<const float4*>(x),
        reinterpret_cast<float4*>(out));
}